// round 1
// baseline (speedup 1.0000x reference)
#include <cuda_runtime.h>
#include <math.h>

#define NB 2
#define NN 512
#define ND 256
#define ED 64
#define TJ 8
#define WSTRIDE 257   // padded smem row stride for weight tiles (conflict-free ld+st)

// Scratch for bias-folded node projections: nq' = x@Wnq.T + bnq + beq, etc.
__device__ float d_nqp[NB * NN * ND];
__device__ float d_nkp[NB * NN * ND];
__device__ float d_nvp[NB * NN * ND];

// ---------------------------------------------------------------------------
// Kernel 1: node projections (tiny: 0.4 GFLOP). One block per (b,n) row.
// Warp w computes outputs [w*32, w*32+32) for q,k,v via coalesced weight reads
// + warp reduction. Biases (node + edge) folded in.
// ---------------------------------------------------------------------------
__global__ __launch_bounds__(256) void node_proj_kernel(
    const float* __restrict__ node,
    const float* __restrict__ Wnq, const float* __restrict__ bnq,
    const float* __restrict__ Wnk, const float* __restrict__ bnk,
    const float* __restrict__ Wnv, const float* __restrict__ bnv,
    const float* __restrict__ beq, const float* __restrict__ bek,
    const float* __restrict__ bev)
{
    __shared__ float xs[ND];
    const int row  = blockIdx.x;           // b*NN + n
    const int tid  = threadIdx.x;
    const int lane = tid & 31;
    const int w    = tid >> 5;

    xs[tid] = node[row * ND + tid];
    __syncthreads();

    for (int oo = 0; oo < 32; oo++) {
        const int o = w * 32 + oo;
        const float* rq = Wnq + o * ND;
        const float* rk = Wnk + o * ND;
        const float* rv = Wnv + o * ND;
        float a0 = 0.f, a1 = 0.f, a2 = 0.f;
        #pragma unroll
        for (int c = lane; c < ND; c += 32) {
            const float x = xs[c];
            a0 += rq[c] * x;
            a1 += rk[c] * x;
            a2 += rv[c] * x;
        }
        #pragma unroll
        for (int sh = 16; sh; sh >>= 1) {
            a0 += __shfl_xor_sync(0xffffffffu, a0, sh);
            a1 += __shfl_xor_sync(0xffffffffu, a1, sh);
            a2 += __shfl_xor_sync(0xffffffffu, a2, sh);
        }
        if (lane == 0) {
            d_nqp[row * ND + o] = a0 + bnq[o] + beq[o];
            d_nkp[row * ND + o] = a1 + bnk[o] + bek[o];
            d_nvp[row * ND + o] = a2 + bnv[o] + bev[o];
        }
    }
}

// ---------------------------------------------------------------------------
// Kernel 2: fused edge-projection + relational attention.
// One CTA per query row (b,i). 256 threads: t = h*32 + d; warp h owns head h.
// Online (flash) softmax over j in tiles of TJ=8. Edge read exactly once.
// ---------------------------------------------------------------------------
__global__ __launch_bounds__(256) void attn_kernel(
    const float* __restrict__ edge,
    const float* __restrict__ Weq,
    const float* __restrict__ Wek,
    const float* __restrict__ Wev,
    float* __restrict__ out)
{
    extern __shared__ float sm[];
    float* Wq_s = sm;                        // [ED][WSTRIDE]
    float* Wk_s = Wq_s + ED * WSTRIDE;
    float* Wv_s = Wk_s + ED * WSTRIDE;
    float* et   = Wv_s + ED * WSTRIDE;       // [ED][TJ] edge tile, transposed
    float* nkt  = et   + ED * TJ;            // [TJ][ND]
    float* nvt  = nkt  + TJ * ND;            // [TJ][ND]

    const int tid = threadIdx.x;
    const int row = blockIdx.x;              // b*NN + i
    const int b   = row >> 9;                // row / NN

    // Load weights transposed into smem: Wq_s[c*WSTRIDE + t] = Weq[t*ED + c].
    // idx = t*ED + c keeps global reads coalesced; WSTRIDE=257 makes the
    // strided smem writes conflict-free (bank = (c + t) % 32).
    for (int idx = tid; idx < ND * ED; idx += 256) {
        const int t = idx >> 6;
        const int c = idx & 63;
        Wq_s[c * WSTRIDE + t] = Weq[idx];
        Wk_s[c * WSTRIDE + t] = Wek[idx];
        Wv_s[c * WSTRIDE + t] = Wev[idx];
    }
    const float qr = d_nqp[row * ND + tid];  // bias-folded query (per t)
    __syncthreads();

    float m = -1e30f;   // running max (lane-uniform within warp/head)
    float l = 0.f;      // running denom
    float o = 0.f;      // running numerator for this (h,d)
    const float scale = 0.17677669529663687f;  // 1/sqrt(32)

    const float* erow = edge + (size_t)row * NN * ED;

    for (int j0 = 0; j0 < NN; j0 += TJ) {
        __syncthreads();
        // Edge tile, transposed: et[c*TJ + jj] = edge[b,i,j0+jj,c]
        #pragma unroll
        for (int idx = tid; idx < TJ * ED; idx += 256) {
            const int jj = idx >> 6;
            const int c  = idx & 63;
            et[c * TJ + jj] = erow[(j0 + jj) * ED + c];
        }
        // Node key/value tiles (bias-folded), coalesced
        #pragma unroll
        for (int idx = tid; idx < TJ * ND; idx += 256) {
            const int jj = idx >> 8;
            const int gj = ((b << 9) + j0 + jj) * ND + (idx & 255);
            nkt[idx] = d_nkp[gj];
            nvt[idx] = d_nvp[gj];
        }
        __syncthreads();

        // Projections: p = Weq*e, k = Wek*e, v = Wev*e for TJ edge vectors.
        float p[TJ], k[TJ], v[TJ];
        #pragma unroll
        for (int jj = 0; jj < TJ; jj++) { p[jj] = 0.f; k[jj] = 0.f; v[jj] = 0.f; }

        const float4* et4 = (const float4*)et;
        #pragma unroll 8
        for (int c = 0; c < ED; c++) {
            const float wq = Wq_s[c * WSTRIDE + tid];
            const float wk = Wk_s[c * WSTRIDE + tid];
            const float wv = Wv_s[c * WSTRIDE + tid];
            const float4 ea = et4[c * 2];
            const float4 eb = et4[c * 2 + 1];
            const float ev8[TJ] = {ea.x, ea.y, ea.z, ea.w, eb.x, eb.y, eb.z, eb.w};
            #pragma unroll
            for (int jj = 0; jj < TJ; jj++) {
                p[jj] += wq * ev8[jj];
                k[jj] += wk * ev8[jj];
                v[jj] += wv * ev8[jj];
            }
        }

        // qk scores: warp h reduces over its 32 lanes (the Dh dim)
        float s[TJ];
        #pragma unroll
        for (int jj = 0; jj < TJ; jj++) {
            float part = (p[jj] + qr) * (k[jj] + nkt[jj * ND + tid]);
            #pragma unroll
            for (int sh = 16; sh; sh >>= 1)
                part += __shfl_xor_sync(0xffffffffu, part, sh);
            s[jj] = part * scale;
        }

        // Online softmax update (lane-uniform state per warp)
        float mt = m;
        #pragma unroll
        for (int jj = 0; jj < TJ; jj++) mt = fmaxf(mt, s[jj]);
        const float alpha = __expf(m - mt);
        o *= alpha;
        l *= alpha;
        m = mt;
        #pragma unroll
        for (int jj = 0; jj < TJ; jj++) {
            const float wj = __expf(s[jj] - m);
            l += wj;
            o += wj * (v[jj] + nvt[jj * ND + tid]);
        }
    }

    out[row * ND + tid] = o / l;
}

// ---------------------------------------------------------------------------
extern "C" void kernel_launch(void* const* d_in, const int* in_sizes, int n_in,
                              void* d_out, int out_size)
{
    const float* node = (const float*)d_in[0];
    const float* edge = (const float*)d_in[1];
    const float* Wnq  = (const float*)d_in[2];
    const float* bnq  = (const float*)d_in[3];
    const float* Wnk  = (const float*)d_in[4];
    const float* bnk  = (const float*)d_in[5];
    const float* Wnv  = (const float*)d_in[6];
    const float* bnv  = (const float*)d_in[7];
    const float* Weq  = (const float*)d_in[8];
    const float* beq  = (const float*)d_in[9];
    const float* Wek  = (const float*)d_in[10];
    const float* bek  = (const float*)d_in[11];
    const float* Wev  = (const float*)d_in[12];
    const float* bev  = (const float*)d_in[13];
    float* out = (float*)d_out;

    const int smem_bytes = (3 * ED * WSTRIDE + ED * TJ + 2 * TJ * ND) * (int)sizeof(float);
    cudaFuncSetAttribute(attn_kernel, cudaFuncAttributeMaxDynamicSharedMemorySize,
                         smem_bytes);

    node_proj_kernel<<<NB * NN, 256>>>(node, Wnq, bnq, Wnk, bnk, Wnv, bnv,
                                       beq, bek, bev);
    attn_kernel<<<NB * NN, 256, smem_bytes>>>(edge, Weq, Wek, Wev, out);
}

// round 3
// speedup vs baseline: 3.2553x; 3.2553x over previous
#include <cuda_runtime.h>
#include <cstdint>
#include <math.h>

#define NB 2
#define NN 512
#define ND 256
#define ED 64
#define NJ 64            // j-chunk
#define NCH (NN / NJ)    // 8 chunks

// smem float offsets
#define OFF_WQ 0
#define OFF_WK 8704
#define OFF_WV 17408
#define OFF_E  26112     // [64][68]
#define OFF_NK 30464     // [64][132]
#define OFF_NV 38912     // [64][132]
#define OFF_NQ 47360     // [128]
#define SMEM_FLOATS 47488
#define SMEM_BYTES (SMEM_FLOATS * 4)

// ---------------------------------------------------------------------------
// Scratch: bias-folded node projections (edge biases folded in too)
// ---------------------------------------------------------------------------
__device__ float d_nqp[NB * NN * ND];
__device__ float d_nkp[NB * NN * ND];
__device__ float d_nvp[NB * NN * ND];

// ---------------------------------------------------------------------------
// Kernel 1: node projections (tiny). One block per (b,n) row.
// ---------------------------------------------------------------------------
__global__ __launch_bounds__(256) void node_proj_kernel(
    const float* __restrict__ node,
    const float* __restrict__ Wnq, const float* __restrict__ bnq,
    const float* __restrict__ Wnk, const float* __restrict__ bnk,
    const float* __restrict__ Wnv, const float* __restrict__ bnv,
    const float* __restrict__ beq, const float* __restrict__ bek,
    const float* __restrict__ bev)
{
    __shared__ float xs[ND];
    const int row  = blockIdx.x;
    const int tid  = threadIdx.x;
    const int lane = tid & 31;
    const int w    = tid >> 5;

    xs[tid] = node[row * ND + tid];
    __syncthreads();

    for (int oo = 0; oo < 32; oo++) {
        const int o = w * 32 + oo;
        const float* rq = Wnq + o * ND;
        const float* rk = Wnk + o * ND;
        const float* rv = Wnv + o * ND;
        float a0 = 0.f, a1 = 0.f, a2 = 0.f;
        #pragma unroll
        for (int c = lane; c < ND; c += 32) {
            const float x = xs[c];
            a0 += rq[c] * x;
            a1 += rk[c] * x;
            a2 += rv[c] * x;
        }
        #pragma unroll
        for (int sh = 16; sh; sh >>= 1) {
            a0 += __shfl_xor_sync(0xffffffffu, a0, sh);
            a1 += __shfl_xor_sync(0xffffffffu, a1, sh);
            a2 += __shfl_xor_sync(0xffffffffu, a2, sh);
        }
        if (lane == 0) {
            d_nqp[row * ND + o] = a0 + bnq[o] + beq[o];
            d_nkp[row * ND + o] = a1 + bnk[o] + bek[o];
            d_nvp[row * ND + o] = a2 + bnv[o] + bev[o];
        }
    }
}

// ---------------------------------------------------------------------------
// mma.sync tf32 m16n8k8 (baseline PTX, works on plain sm_103)
// ---------------------------------------------------------------------------
__device__ __forceinline__ void mma_tf32(float c[4],
    uint32_t a0, uint32_t a1, uint32_t a2, uint32_t a3,
    uint32_t b0, uint32_t b1)
{
    asm volatile(
        "mma.sync.aligned.m16n8k8.row.col.f32.tf32.tf32.f32 "
        "{%0,%1,%2,%3}, {%4,%5,%6,%7}, {%8,%9}, {%0,%1,%2,%3};"
        : "+f"(c[0]), "+f"(c[1]), "+f"(c[2]), "+f"(c[3])
        : "r"(a0), "r"(a1), "r"(a2), "r"(a3), "r"(b0), "r"(b1));
}

__device__ __forceinline__ uint32_t to_tf32(float v) {
    uint32_t u;
    asm("cvt.rna.tf32.f32 %0, %1;" : "=r"(u) : "f"(v));
    return u;
}

// D[64 j, 32 t-per-warp] += E[64,64] @ W[32,64]^T  (tf32)
// E_s: [64][68] row=j col=c (tf32 bits); W_s: [128][68] row=t col=c (tf32 bits)
__device__ __forceinline__ void gemm64(float c[4][4][4],
    const float* __restrict__ E_s, const float* __restrict__ W_s,
    int w, int g, int tg)
{
    #pragma unroll
    for (int ks = 0; ks < 8; ks++) {
        uint32_t b0[4], b1[4];
        #pragma unroll
        for (int nt = 0; nt < 4; nt++) {
            const float* bp = W_s + (w * 32 + nt * 8 + g) * 68 + ks * 8 + tg;
            b0[nt] = __float_as_uint(bp[0]);
            b1[nt] = __float_as_uint(bp[4]);
        }
        #pragma unroll
        for (int mt = 0; mt < 4; mt++) {
            const float* ap = E_s + (mt * 16 + g) * 68 + ks * 8 + tg;
            const uint32_t a0 = __float_as_uint(ap[0]);
            const uint32_t a1 = __float_as_uint(ap[8 * 68]);
            const uint32_t a2 = __float_as_uint(ap[4]);
            const uint32_t a3 = __float_as_uint(ap[8 * 68 + 4]);
            #pragma unroll
            for (int nt = 0; nt < 4; nt++)
                mma_tf32(c[mt][nt], a0, a1, a2, a3, b0[nt], b1[nt]);
        }
    }
}

// ---------------------------------------------------------------------------
// Kernel 2: fused edge projections (tensor-core tf32) + relational attention.
// CTA = (row, half): blockIdx.x = row*2 + half. 128 threads / 4 warps.
// Warp w owns head half*4+w (t-slice of 32 = the MMA N dimension).
// ---------------------------------------------------------------------------
__global__ __launch_bounds__(128, 1) void attn_mma_kernel(
    const float* __restrict__ edge,
    const float* __restrict__ Weq, const float* __restrict__ Wek,
    const float* __restrict__ Wev,
    float* __restrict__ out)
{
    extern __shared__ float S[];
    float* Wq_s = S + OFF_WQ;
    float* Wk_s = S + OFF_WK;
    float* Wv_s = S + OFF_WV;
    float* E_s  = S + OFF_E;
    float* NK_s = S + OFF_NK;
    float* NV_s = S + OFF_NV;
    float* nq_s = S + OFF_NQ;

    const int bx   = blockIdx.x;
    const int row  = bx >> 1;
    const int half = bx & 1;
    const int b    = row >> 9;
    const int tid  = threadIdx.x;
    const int w    = tid >> 5;
    const int lane = tid & 31;
    const int g    = lane >> 2;     // groupID
    const int tg   = lane & 3;      // thread-in-group
    const float scale = 0.17677669529663687f;   // 1/sqrt(32)

    // ---- weight fill (scale folded into Wq), tf32-rounded ----
    #pragma unroll 4
    for (int idx = tid; idx < 128 * 64; idx += 128) {
        const int t = idx >> 6, c = idx & 63;
        const int gi = (half * 128 + t) * 64 + c;
        Wq_s[t * 68 + c] = __uint_as_float(to_tf32(Weq[gi] * scale));
        Wk_s[t * 68 + c] = __uint_as_float(to_tf32(Wek[gi]));
        Wv_s[t * 68 + c] = __uint_as_float(to_tf32(Wev[gi]));
    }
    if (tid < 128)
        nq_s[tid] = d_nqp[row * ND + half * 128 + tid] * scale;

    float m_run = -1e30f, l_run = 0.f;
    float o[8];
    #pragma unroll
    for (int i = 0; i < 8; i++) o[i] = 0.f;

    const float* erow = edge + (size_t)row * NN * ED;

    for (int ch = 0; ch < NCH; ch++) {
        const int j0 = ch * NJ;
        __syncthreads();   // previous chunk fully consumed; fills visible

        // ---- E chunk fill (tf32-rounded), [64 j][68 stride] ----
        #pragma unroll
        for (int it = 0; it < 8; it++) {
            const int idx = it * 128 + tid;
            const int j = idx >> 4, c4 = idx & 15;
            const float4 v = *(const float4*)(erow + (size_t)(j0 + j) * ED + c4 * 4);
            float4 r;
            r.x = __uint_as_float(to_tf32(v.x));
            r.y = __uint_as_float(to_tf32(v.y));
            r.z = __uint_as_float(to_tf32(v.z));
            r.w = __uint_as_float(to_tf32(v.w));
            *(float4*)(E_s + j * 68 + c4 * 4) = r;
        }
        // ---- nk/nv staging, [64 j][132 stride] (exact fp32) ----
        #pragma unroll
        for (int it = 0; it < 16; it++) {
            const int idx = it * 128 + tid;
            const int j = idx >> 5, t4 = idx & 31;
            const size_t gi = ((size_t)(b * NN + j0 + j)) * ND + half * 128 + t4 * 4;
            *(float4*)(NK_s + j * 132 + t4 * 4) = *(const float4*)(d_nkp + gi);
            *(float4*)(NV_s + j * 132 + t4 * 4) = *(const float4*)(d_nvp + gi);
        }
        __syncthreads();

        // ---- Q~ = scale*(nq + E@Wq^T) : accum init = scale*nq ----
        float cq[4][4][4];
        #pragma unroll
        for (int mt = 0; mt < 4; mt++)
            #pragma unroll
            for (int nt = 0; nt < 4; nt++) {
                const int t0 = w * 32 + nt * 8 + 2 * tg;
                cq[mt][nt][0] = nq_s[t0];
                cq[mt][nt][1] = nq_s[t0 + 1];
                cq[mt][nt][2] = cq[mt][nt][0];
                cq[mt][nt][3] = cq[mt][nt][1];
            }
        gemm64(cq, E_s, Wq_s, w, g, tg);

        // ---- K~ = nk + E@Wk^T : accum init = nk[j][t] ----
        float ck[4][4][4];
        #pragma unroll
        for (int mt = 0; mt < 4; mt++)
            #pragma unroll
            for (int nt = 0; nt < 4; nt++) {
                const int jA = mt * 16 + g;
                const int t0 = w * 32 + nt * 8 + 2 * tg;
                ck[mt][nt][0] = NK_s[jA * 132 + t0];
                ck[mt][nt][1] = NK_s[jA * 132 + t0 + 1];
                ck[mt][nt][2] = NK_s[(jA + 8) * 132 + t0];
                ck[mt][nt][3] = NK_s[(jA + 8) * 132 + t0 + 1];
            }
        gemm64(ck, E_s, Wk_s, w, g, tg);

        // ---- scores: s[j] = sum_t Q~*K~ (t over warp's 32 dims) ----
        float s0[4], s1[4];
        #pragma unroll
        for (int mt = 0; mt < 4; mt++) {
            float a = 0.f, bb2 = 0.f;
            #pragma unroll
            for (int nt = 0; nt < 4; nt++) {
                a   = fmaf(cq[mt][nt][0], ck[mt][nt][0], a);
                a   = fmaf(cq[mt][nt][1], ck[mt][nt][1], a);
                bb2 = fmaf(cq[mt][nt][2], ck[mt][nt][2], bb2);
                bb2 = fmaf(cq[mt][nt][3], ck[mt][nt][3], bb2);
            }
            a   += __shfl_xor_sync(0xffffffffu, a, 1);
            a   += __shfl_xor_sync(0xffffffffu, a, 2);
            bb2 += __shfl_xor_sync(0xffffffffu, bb2, 1);
            bb2 += __shfl_xor_sync(0xffffffffu, bb2, 2);
            s0[mt] = a;      // j = j0 + mt*16 + g
            s1[mt] = bb2;    // j = j0 + mt*16 + g + 8
        }

        // ---- online softmax (warp-uniform state) ----
        float mx = -1e30f;
        #pragma unroll
        for (int mt = 0; mt < 4; mt++) mx = fmaxf(mx, fmaxf(s0[mt], s1[mt]));
        mx = fmaxf(mx, __shfl_xor_sync(0xffffffffu, mx, 4));
        mx = fmaxf(mx, __shfl_xor_sync(0xffffffffu, mx, 8));
        mx = fmaxf(mx, __shfl_xor_sync(0xffffffffu, mx, 16));
        const float mnew  = fmaxf(m_run, mx);
        const float alpha = __expf(m_run - mnew);
        m_run = mnew;

        float w0[4], w1[4], ls = 0.f;
        #pragma unroll
        for (int mt = 0; mt < 4; mt++) {
            w0[mt] = __expf(s0[mt] - mnew);
            w1[mt] = __expf(s1[mt] - mnew);
            ls += w0[mt] + w1[mt];
        }
        ls += __shfl_xor_sync(0xffffffffu, ls, 4);
        ls += __shfl_xor_sync(0xffffffffu, ls, 8);
        ls += __shfl_xor_sync(0xffffffffu, ls, 16);
        l_run = l_run * alpha + ls;
        #pragma unroll
        for (int i = 0; i < 8; i++) o[i] *= alpha;

        // ---- V~ = nv + E@Wv^T, then o[t] += sum_j w(j) V~(j,t) ----
        float cv[4][4][4];
        #pragma unroll
        for (int mt = 0; mt < 4; mt++)
            #pragma unroll
            for (int nt = 0; nt < 4; nt++) {
                const int jA = mt * 16 + g;
                const int t0 = w * 32 + nt * 8 + 2 * tg;
                cv[mt][nt][0] = NV_s[jA * 132 + t0];
                cv[mt][nt][1] = NV_s[jA * 132 + t0 + 1];
                cv[mt][nt][2] = NV_s[(jA + 8) * 132 + t0];
                cv[mt][nt][3] = NV_s[(jA + 8) * 132 + t0 + 1];
            }
        gemm64(cv, E_s, Wv_s, w, g, tg);

        #pragma unroll
        for (int nt = 0; nt < 4; nt++)
            #pragma unroll
            for (int mt = 0; mt < 4; mt++) {
                o[nt * 2]     = fmaf(w0[mt], cv[mt][nt][0], o[nt * 2]);
                o[nt * 2]     = fmaf(w1[mt], cv[mt][nt][2], o[nt * 2]);
                o[nt * 2 + 1] = fmaf(w0[mt], cv[mt][nt][1], o[nt * 2 + 1]);
                o[nt * 2 + 1] = fmaf(w1[mt], cv[mt][nt][3], o[nt * 2 + 1]);
            }
    }

    // deferred reduction over g lanes (j ≡ g mod 8 partials)
    #pragma unroll
    for (int i = 0; i < 8; i++) {
        float v = o[i];
        v += __shfl_xor_sync(0xffffffffu, v, 4);
        v += __shfl_xor_sync(0xffffffffu, v, 8);
        v += __shfl_xor_sync(0xffffffffu, v, 16);
        o[i] = v;
    }
    if (g == 0) {
        const float inv = 1.f / l_run;
        #pragma unroll
        for (int nt = 0; nt < 4; nt++) {
            const int t = half * 128 + w * 32 + nt * 8 + 2 * tg;
            out[row * ND + t]     = o[nt * 2]     * inv;
            out[row * ND + t + 1] = o[nt * 2 + 1] * inv;
        }
    }
}

// ---------------------------------------------------------------------------
extern "C" void kernel_launch(void* const* d_in, const int* in_sizes, int n_in,
                              void* d_out, int out_size)
{
    const float* node = (const float*)d_in[0];
    const float* edge = (const float*)d_in[1];
    const float* Wnq  = (const float*)d_in[2];
    const float* bnq  = (const float*)d_in[3];
    const float* Wnk  = (const float*)d_in[4];
    const float* bnk  = (const float*)d_in[5];
    const float* Wnv  = (const float*)d_in[6];
    const float* bnv  = (const float*)d_in[7];
    const float* Weq  = (const float*)d_in[8];
    const float* beq  = (const float*)d_in[9];
    const float* Wek  = (const float*)d_in[10];
    const float* bek  = (const float*)d_in[11];
    const float* Wev  = (const float*)d_in[12];
    const float* bev  = (const float*)d_in[13];
    float* out = (float*)d_out;

    cudaFuncSetAttribute(attn_mma_kernel,
                         cudaFuncAttributeMaxDynamicSharedMemorySize, SMEM_BYTES);

    node_proj_kernel<<<NB * NN, 256>>>(node, Wnq, bnq, Wnk, bnk, Wnv, bnv,
                                       beq, bek, bev);
    attn_mma_kernel<<<NB * NN * 2, 128, SMEM_BYTES>>>(edge, Weq, Wek, Wev, out);
}

// round 4
// speedup vs baseline: 4.6433x; 1.4264x over previous
#include <cuda_runtime.h>
#include <cuda_fp16.h>
#include <cstdint>
#include <math.h>

#define NB 2
#define NN 512
#define ND 256
#define ED 64
#define NJ 32            // j-chunk
#define NCH (NN / NJ)    // 16 chunks
#define WS 72            // smem stride in halves (conflict-free: bank = 4g+tg)

// smem half offsets
#define OFF_WQ 0
#define OFF_WK (128 * WS)
#define OFF_WV (2 * 128 * WS)
#define OFF_E  (3 * 128 * WS)
#define OFF_NQ (3 * 128 * WS + NJ * WS)      // halves; 4-byte aligned
#define SMEM_BYTES (OFF_NQ * 2 + 128 * 4)

// ---------------------------------------------------------------------------
// Scratch: bias-folded node projections (edge biases folded in too)
// ---------------------------------------------------------------------------
__device__ float d_nqp[NB * NN * ND];
__device__ float d_nkp[NB * NN * ND];
__device__ float d_nvp[NB * NN * ND];

// ---------------------------------------------------------------------------
// Kernel 1: node projections (tiny). One block per (b,n) row.
// ---------------------------------------------------------------------------
__global__ __launch_bounds__(256) void node_proj_kernel(
    const float* __restrict__ node,
    const float* __restrict__ Wnq, const float* __restrict__ bnq,
    const float* __restrict__ Wnk, const float* __restrict__ bnk,
    const float* __restrict__ Wnv, const float* __restrict__ bnv,
    const float* __restrict__ beq, const float* __restrict__ bek,
    const float* __restrict__ bev)
{
    __shared__ float xs[ND];
    const int row  = blockIdx.x;
    const int tid  = threadIdx.x;
    const int lane = tid & 31;
    const int w    = tid >> 5;

    xs[tid] = node[row * ND + tid];
    __syncthreads();

    for (int oo = 0; oo < 32; oo++) {
        const int o = w * 32 + oo;
        const float* rq = Wnq + o * ND;
        const float* rk = Wnk + o * ND;
        const float* rv = Wnv + o * ND;
        float a0 = 0.f, a1 = 0.f, a2 = 0.f;
        #pragma unroll
        for (int c = lane; c < ND; c += 32) {
            const float x = xs[c];
            a0 += rq[c] * x;
            a1 += rk[c] * x;
            a2 += rv[c] * x;
        }
        #pragma unroll
        for (int sh = 16; sh; sh >>= 1) {
            a0 += __shfl_xor_sync(0xffffffffu, a0, sh);
            a1 += __shfl_xor_sync(0xffffffffu, a1, sh);
            a2 += __shfl_xor_sync(0xffffffffu, a2, sh);
        }
        if (lane == 0) {
            d_nqp[row * ND + o] = a0 + bnq[o] + beq[o];
            d_nkp[row * ND + o] = a1 + bnk[o] + bek[o];
            d_nvp[row * ND + o] = a2 + bnv[o] + bev[o];
        }
    }
}

// ---------------------------------------------------------------------------
// mma.sync fp16 m16n8k16, fp32 accumulate (baseline PTX, plain sm_103 OK)
// ---------------------------------------------------------------------------
__device__ __forceinline__ void mma_f16(float c[4],
    uint32_t a0, uint32_t a1, uint32_t a2, uint32_t a3,
    uint32_t b0, uint32_t b1)
{
    asm volatile(
        "mma.sync.aligned.m16n8k16.row.col.f32.f16.f16.f32 "
        "{%0,%1,%2,%3}, {%4,%5,%6,%7}, {%8,%9}, {%0,%1,%2,%3};"
        : "+f"(c[0]), "+f"(c[1]), "+f"(c[2]), "+f"(c[3])
        : "r"(a0), "r"(a1), "r"(a2), "r"(a3), "r"(b0), "r"(b1));
}

// D[32 j, 32 t-per-warp] += E[32,64] @ W[32,64]^T  (fp16 in, fp32 acc)
// E_s: [32][WS] row=j col=c; W_s: [128][WS] row=t col=c
__device__ __forceinline__ void gemm32(float c[2][4][4],
    const __half* __restrict__ E_s, const __half* __restrict__ W_s,
    int w, int g, int tg)
{
    #pragma unroll
    for (int ks = 0; ks < 4; ks++) {
        uint32_t b0[4], b1[4];
        #pragma unroll
        for (int nt = 0; nt < 4; nt++) {
            const __half* bp = W_s + (w * 32 + nt * 8 + g) * WS + ks * 16 + 2 * tg;
            b0[nt] = *(const uint32_t*)bp;
            b1[nt] = *(const uint32_t*)(bp + 8);
        }
        #pragma unroll
        for (int mt = 0; mt < 2; mt++) {
            const __half* ap = E_s + (mt * 16 + g) * WS + ks * 16 + 2 * tg;
            const uint32_t a0 = *(const uint32_t*)ap;
            const uint32_t a1 = *(const uint32_t*)(ap + 8 * WS);
            const uint32_t a2 = *(const uint32_t*)(ap + 8);
            const uint32_t a3 = *(const uint32_t*)(ap + 8 * WS + 8);
            #pragma unroll
            for (int nt = 0; nt < 4; nt++)
                mma_f16(c[mt][nt], a0, a1, a2, a3, b0[nt], b1[nt]);
        }
    }
}

// ---------------------------------------------------------------------------
// Kernel 2: fused edge projections (fp16 tensor core) + relational attention.
// CTA = (row, half): blockIdx.x = row*2 + half. 128 threads / 4 warps.
// Warp w owns head half*4+w. 3 CTAs/SM.
// ---------------------------------------------------------------------------
__global__ __launch_bounds__(128, 3) void attn_mma_kernel(
    const float* __restrict__ edge,
    const float* __restrict__ Weq, const float* __restrict__ Wek,
    const float* __restrict__ Wev,
    float* __restrict__ out)
{
    extern __shared__ __half S[];
    __half* Wq_s = S + OFF_WQ;
    __half* Wk_s = S + OFF_WK;
    __half* Wv_s = S + OFF_WV;
    __half* E_s  = S + OFF_E;
    float*  nq_s = (float*)(S + OFF_NQ);

    const int bx   = blockIdx.x;
    const int row  = bx >> 1;
    const int half = bx & 1;
    const int b    = row >> 9;
    const int tid  = threadIdx.x;
    const int w    = tid >> 5;
    const int lane = tid & 31;
    const int g    = lane >> 2;     // groupID
    const int tg   = lane & 3;      // thread-in-group
    const float scale = 0.17677669529663687f;   // 1/sqrt(32)

    // ---- weight fill (scale folded into Wq), fp16 ----
    #pragma unroll 4
    for (int idx = tid; idx < 128 * 32; idx += 128) {
        const int t = idx >> 5, c2 = idx & 31;       // c2 indexes half2
        const float2 q = *(const float2*)(Weq + (half * 128 + t) * 64 + c2 * 2);
        const float2 k = *(const float2*)(Wek + (half * 128 + t) * 64 + c2 * 2);
        const float2 v = *(const float2*)(Wev + (half * 128 + t) * 64 + c2 * 2);
        *(__half2*)(Wq_s + t * WS + c2 * 2) = __floats2half2_rn(q.x * scale, q.y * scale);
        *(__half2*)(Wk_s + t * WS + c2 * 2) = __floats2half2_rn(k.x, k.y);
        *(__half2*)(Wv_s + t * WS + c2 * 2) = __floats2half2_rn(v.x, v.y);
    }
    nq_s[tid] = d_nqp[row * ND + half * 128 + tid] * scale;

    float m_run = -1e30f, l_run = 0.f;
    float o[8];
    #pragma unroll
    for (int i = 0; i < 8; i++) o[i] = 0.f;

    const float* erow = edge + (size_t)row * NN * ED;
    const int t0b = w * 32 + 2 * tg;     // base t for this thread (col pairs)

    for (int ch = 0; ch < NCH; ch++) {
        const int j0 = ch * NJ;
        __syncthreads();

        // ---- E chunk fill -> fp16 [32][WS] ----
        #pragma unroll
        for (int it = 0; it < 8; it++) {
            const int idx = it * 128 + tid;
            const int j = idx >> 5, c2 = idx & 31;
            const float2 v = *(const float2*)(erow + (size_t)(j0 + j) * ED + c2 * 2);
            *(__half2*)(E_s + j * WS + c2 * 2) = __floats2half2_rn(v.x, v.y);
        }
        __syncthreads();

        // ---- Q~ = scale*(nq + E@Wq^T) : accum init = scale*nq ----
        float cq[2][4][4];
        #pragma unroll
        for (int mt = 0; mt < 2; mt++)
            #pragma unroll
            for (int nt = 0; nt < 4; nt++) {
                const int t0 = t0b + nt * 8;
                cq[mt][nt][0] = nq_s[t0];
                cq[mt][nt][1] = nq_s[t0 + 1];
                cq[mt][nt][2] = cq[mt][nt][0];
                cq[mt][nt][3] = cq[mt][nt][1];
            }
        gemm32(cq, E_s, Wq_s, w, g, tg);

        // ---- K~ = nk + E@Wk^T : accum init = nk[j][t] (direct L2 loads) ----
        const float* nkb = d_nkp + (size_t)(b * NN + j0) * ND + half * 128;
        float ck[2][4][4];
        #pragma unroll
        for (int mt = 0; mt < 2; mt++) {
            const int jA = mt * 16 + g;
            #pragma unroll
            for (int nt = 0; nt < 4; nt++) {
                const int t0 = t0b + nt * 8;
                const float2 v0 = *(const float2*)(nkb + (size_t)jA * ND + t0);
                const float2 v1 = *(const float2*)(nkb + (size_t)(jA + 8) * ND + t0);
                ck[mt][nt][0] = v0.x; ck[mt][nt][1] = v0.y;
                ck[mt][nt][2] = v1.x; ck[mt][nt][3] = v1.y;
            }
        }
        gemm32(ck, E_s, Wk_s, w, g, tg);

        // ---- scores: s[j] = sum_t Q~*K~ (t over warp's 32 dims) ----
        float s0[2], s1[2];
        #pragma unroll
        for (int mt = 0; mt < 2; mt++) {
            float a = 0.f, bb = 0.f;
            #pragma unroll
            for (int nt = 0; nt < 4; nt++) {
                a  = fmaf(cq[mt][nt][0], ck[mt][nt][0], a);
                a  = fmaf(cq[mt][nt][1], ck[mt][nt][1], a);
                bb = fmaf(cq[mt][nt][2], ck[mt][nt][2], bb);
                bb = fmaf(cq[mt][nt][3], ck[mt][nt][3], bb);
            }
            a  += __shfl_xor_sync(0xffffffffu, a, 1);
            a  += __shfl_xor_sync(0xffffffffu, a, 2);
            bb += __shfl_xor_sync(0xffffffffu, bb, 1);
            bb += __shfl_xor_sync(0xffffffffu, bb, 2);
            s0[mt] = a;      // j = j0 + mt*16 + g
            s1[mt] = bb;     // j = j0 + mt*16 + g + 8
        }

        // ---- online softmax (warp-uniform state) ----
        float mx = fmaxf(fmaxf(s0[0], s1[0]), fmaxf(s0[1], s1[1]));
        mx = fmaxf(mx, __shfl_xor_sync(0xffffffffu, mx, 4));
        mx = fmaxf(mx, __shfl_xor_sync(0xffffffffu, mx, 8));
        mx = fmaxf(mx, __shfl_xor_sync(0xffffffffu, mx, 16));
        const float mnew  = fmaxf(m_run, mx);
        const float alpha = __expf(m_run - mnew);
        m_run = mnew;

        float w0[2], w1[2], ls = 0.f;
        #pragma unroll
        for (int mt = 0; mt < 2; mt++) {
            w0[mt] = __expf(s0[mt] - mnew);
            w1[mt] = __expf(s1[mt] - mnew);
            ls += w0[mt] + w1[mt];
        }
        ls += __shfl_xor_sync(0xffffffffu, ls, 4);
        ls += __shfl_xor_sync(0xffffffffu, ls, 8);
        ls += __shfl_xor_sync(0xffffffffu, ls, 16);
        l_run = l_run * alpha + ls;
        #pragma unroll
        for (int i = 0; i < 8; i++) o[i] *= alpha;

        // ---- V~ = nv + E@Wv^T, then o[t] += sum_j w(j) V~(j,t) ----
        const float* nvb = d_nvp + (size_t)(b * NN + j0) * ND + half * 128;
        float cv[2][4][4];
        #pragma unroll
        for (int mt = 0; mt < 2; mt++) {
            const int jA = mt * 16 + g;
            #pragma unroll
            for (int nt = 0; nt < 4; nt++) {
                const int t0 = t0b + nt * 8;
                const float2 v0 = *(const float2*)(nvb + (size_t)jA * ND + t0);
                const float2 v1 = *(const float2*)(nvb + (size_t)(jA + 8) * ND + t0);
                cv[mt][nt][0] = v0.x; cv[mt][nt][1] = v0.y;
                cv[mt][nt][2] = v1.x; cv[mt][nt][3] = v1.y;
            }
        }
        gemm32(cv, E_s, Wv_s, w, g, tg);

        #pragma unroll
        for (int nt = 0; nt < 4; nt++)
            #pragma unroll
            for (int mt = 0; mt < 2; mt++) {
                o[nt * 2]     = fmaf(w0[mt], cv[mt][nt][0], o[nt * 2]);
                o[nt * 2]     = fmaf(w1[mt], cv[mt][nt][2], o[nt * 2]);
                o[nt * 2 + 1] = fmaf(w0[mt], cv[mt][nt][1], o[nt * 2 + 1]);
                o[nt * 2 + 1] = fmaf(w1[mt], cv[mt][nt][3], o[nt * 2 + 1]);
            }
    }

    // deferred reduction over g lanes (j ≡ g mod 8 partials)
    #pragma unroll
    for (int i = 0; i < 8; i++) {
        float v = o[i];
        v += __shfl_xor_sync(0xffffffffu, v, 4);
        v += __shfl_xor_sync(0xffffffffu, v, 8);
        v += __shfl_xor_sync(0xffffffffu, v, 16);
        o[i] = v;
    }
    if (g == 0) {
        const float inv = 1.f / l_run;
        #pragma unroll
        for (int nt = 0; nt < 4; nt++) {
            const int t = half * 128 + w * 32 + nt * 8 + 2 * tg;
            out[row * ND + t]     = o[nt * 2]     * inv;
            out[row * ND + t + 1] = o[nt * 2 + 1] * inv;
        }
    }
}

// ---------------------------------------------------------------------------
extern "C" void kernel_launch(void* const* d_in, const int* in_sizes, int n_in,
                              void* d_out, int out_size)
{
    const float* node = (const float*)d_in[0];
    const float* edge = (const float*)d_in[1];
    const float* Wnq  = (const float*)d_in[2];
    const float* bnq  = (const float*)d_in[3];
    const float* Wnk  = (const float*)d_in[4];
    const float* bnk  = (const float*)d_in[5];
    const float* Wnv  = (const float*)d_in[6];
    const float* bnv  = (const float*)d_in[7];
    const float* Weq  = (const float*)d_in[8];
    const float* beq  = (const float*)d_in[9];
    const float* Wek  = (const float*)d_in[10];
    const float* bek  = (const float*)d_in[11];
    const float* Wev  = (const float*)d_in[12];
    const float* bev  = (const float*)d_in[13];
    float* out = (float*)d_out;

    cudaFuncSetAttribute(attn_mma_kernel,
                         cudaFuncAttributeMaxDynamicSharedMemorySize, SMEM_BYTES);

    node_proj_kernel<<<NB * NN, 256>>>(node, Wnq, bnq, Wnk, bnk, Wnv, bnv,
                                       beq, bek, bev);
    attn_mma_kernel<<<NB * NN * 2, 128, SMEM_BYTES>>>(edge, Weq, Wek, Wev, out);
}

// round 6
// speedup vs baseline: 4.7295x; 1.0186x over previous
#include <cuda_runtime.h>
#include <cuda_fp16.h>
#include <cstdint>
#include <math.h>

#define NB 2
#define NN 512
#define ND 256
#define ED 64
#define NJ 32            // j-chunk
#define NCH (NN / NJ)    // 16 chunks
#define IB 8             // query rows per CTA

// smem byte offsets (dynamic smem)
#define OFF_E   0u                       // IB x [32 j][72 h] fp16 (4608B per row)
#define OFF_NK  36864u                   // [32 j][136 h] fp16
#define OFF_NV  45568u                   // [32 j][136 h] fp16
#define OFF_NQ  54272u                   // IB x [128] f32 (scaled)
#define OFF_WSB 58368u                   // [4 w][32 j] f32
#define OFF_Z   58880u                   // [4 w][IB][64] f32
#define OFF_ON  67072u                   // [4 w][IB][32] f32
#define OFF_ML  71168u                   // [4 w][IB][2] f32
#define SMEM_BYTES 71680u

// ---------------------------------------------------------------------------
__device__ float d_nqp[NB * NN * ND];
__device__ float d_nkp[NB * NN * ND];
__device__ float d_nvp[NB * NN * ND];

// ---------------------------------------------------------------------------
// Kernel 1: node projections, 8 rows per block (weight traffic amortized 8x).
// Warp w computes outputs [32w, 32w+32) for all 8 rows, q/k/v.
// ---------------------------------------------------------------------------
__global__ __launch_bounds__(256, 2) void node_proj_kernel(
    const float* __restrict__ node,
    const float* __restrict__ Wnq, const float* __restrict__ bnq,
    const float* __restrict__ Wnk, const float* __restrict__ bnk,
    const float* __restrict__ Wnv, const float* __restrict__ bnv,
    const float* __restrict__ beq, const float* __restrict__ bek,
    const float* __restrict__ bev)
{
    const int r0   = blockIdx.x * 8;
    const int tid  = threadIdx.x;
    const int lane = tid & 31;
    const int w    = tid >> 5;

    // register-cached x: xr[r][s] = node[(r0+r)*256 + lane + 32*s]
    float xr[8][8];
    #pragma unroll
    for (int r = 0; r < 8; r++)
        #pragma unroll
        for (int s = 0; s < 8; s++)
            xr[r][s] = node[(size_t)(r0 + r) * ND + lane + 32 * s];

    for (int oo = 0; oo < 32; oo++) {
        const int o = w * 32 + oo;
        float aq[8], ak[8], av[8];
        #pragma unroll
        for (int r = 0; r < 8; r++) { aq[r] = 0.f; ak[r] = 0.f; av[r] = 0.f; }

        #pragma unroll
        for (int s = 0; s < 8; s++) {
            const float wq = Wnq[(size_t)o * ND + lane + 32 * s];
            const float wk = Wnk[(size_t)o * ND + lane + 32 * s];
            const float wv = Wnv[(size_t)o * ND + lane + 32 * s];
            #pragma unroll
            for (int r = 0; r < 8; r++) {
                aq[r] = fmaf(wq, xr[r][s], aq[r]);
                ak[r] = fmaf(wk, xr[r][s], ak[r]);
                av[r] = fmaf(wv, xr[r][s], av[r]);
            }
        }
        #pragma unroll
        for (int r = 0; r < 8; r++) {
            #pragma unroll
            for (int sh = 16; sh; sh >>= 1) {
                aq[r] += __shfl_xor_sync(0xffffffffu, aq[r], sh);
                ak[r] += __shfl_xor_sync(0xffffffffu, ak[r], sh);
                av[r] += __shfl_xor_sync(0xffffffffu, av[r], sh);
            }
        }
        if (lane == 0) {
            const float bq = bnq[o] + beq[o];
            const float bk = bnk[o] + bek[o];
            const float bv = bnv[o] + bev[o];
            #pragma unroll
            for (int r = 0; r < 8; r++) {
                const size_t idx = (size_t)(r0 + r) * ND + o;
                d_nqp[idx] = aq[r] + bq;
                d_nkp[idx] = ak[r] + bk;
                d_nvp[idx] = av[r] + bv;
            }
        }
    }
}

// ---------------------------------------------------------------------------
__device__ __forceinline__ void mma_f16(float c[4],
    uint32_t a0, uint32_t a1, uint32_t a2, uint32_t a3,
    uint32_t b0, uint32_t b1)
{
    asm volatile(
        "mma.sync.aligned.m16n8k16.row.col.f32.f16.f16.f32 "
        "{%0,%1,%2,%3}, {%4,%5,%6,%7}, {%8,%9}, {%0,%1,%2,%3};"
        : "+f"(c[0]), "+f"(c[1]), "+f"(c[2]), "+f"(c[3])
        : "r"(a0), "r"(a1), "r"(a2), "r"(a3), "r"(b0), "r"(b1));
}

__device__ __forceinline__ uint32_t packh2(float a, float b) {
    const __half2 h = __floats2half2_rn(a, b);
    return *(const uint32_t*)&h;
}

// ---------------------------------------------------------------------------
// Kernel 2: fused attention, IB=8 rows per CTA, weights in registers,
// V-gemm eliminated via z-accumulation.
// CTA: 128 threads / 4 warps; warp w owns head (half*4 + w).
// blockIdx.x = b*128 + ib*2 + half; rows i0 = ib*8.
// ---------------------------------------------------------------------------
__global__ __launch_bounds__(128, 2) void attn_mma_kernel(
    const float* __restrict__ edge,
    const float* __restrict__ Weq, const float* __restrict__ Wek,
    const float* __restrict__ Wev,
    float* __restrict__ out)
{
    extern __shared__ char S[];
    __half2* E2  = (__half2*)(S + OFF_E);    // [r*1152 + j*36 + c2]
    __half*  E16 = (__half*)(S + OFF_E);
    __half2* NK2 = (__half2*)(S + OFF_NK);   // [j*68 + t2]
    __half2* NV2 = (__half2*)(S + OFF_NV);
    __half*  NV16= (__half*)(S + OFF_NV);    // [j*136 + t]
    float*   nq_s = (float*)(S + OFF_NQ);    // [r*128 + t]
    float*   ws   = (float*)(S + OFF_WSB);   // [w*32 + j]
    float*   z_s  = (float*)(S + OFF_Z);     // [(w*IB + r)*64 + c]
    float*   on_s = (float*)(S + OFF_ON);    // [(w*IB + r)*32 + lane]
    float*   ml_s = (float*)(S + OFF_ML);    // [(w*IB + r)*2 + {m,l}]

    const int bx   = blockIdx.x;
    const int half = bx & 1;
    const int ib   = (bx >> 1) & 63;
    const int b    = bx >> 7;
    const int i0   = ib * IB;
    const int tid  = threadIdx.x;
    const int w    = tid >> 5;
    const int lane = tid & 31;
    const int g    = lane >> 2;
    const int tg   = lane & 3;
    const float scale = 0.17677669529663687f;

    // ---- B fragments in registers (Wq scaled, Wk), fp16 ----
    uint32_t bq[4][4][2], bk[4][4][2];   // [nt][ks][b0/b1]
    #pragma unroll
    for (int nt = 0; nt < 4; nt++) {
        const size_t rowq = (size_t)(half * 128 + w * 32 + nt * 8 + g) * ED;
        #pragma unroll
        for (int ks = 0; ks < 4; ks++) {
            const float2 q0 = *(const float2*)(Weq + rowq + ks * 16 + 2 * tg);
            const float2 q1 = *(const float2*)(Weq + rowq + ks * 16 + 2 * tg + 8);
            const float2 k0 = *(const float2*)(Wek + rowq + ks * 16 + 2 * tg);
            const float2 k1 = *(const float2*)(Wek + rowq + ks * 16 + 2 * tg + 8);
            bq[nt][ks][0] = packh2(q0.x * scale, q0.y * scale);
            bq[nt][ks][1] = packh2(q1.x * scale, q1.y * scale);
            bk[nt][ks][0] = packh2(k0.x, k0.y);
            bk[nt][ks][1] = packh2(k1.x, k1.y);
        }
    }

    // ---- nq (scaled) for 8 rows ----
    #pragma unroll
    for (int it = 0; it < IB; it++) {
        const int r = it, t = tid;
        if (t < 128)
            nq_s[r * 128 + t] =
                d_nqp[(size_t)(b * NN + i0 + r) * ND + half * 128 + t] * scale;
    }
    // ---- init per-row state ----
    for (int f = tid; f < 4 * IB * 64; f += 128) z_s[f] = 0.f;
    for (int f = tid; f < 4 * IB * 32; f += 128) on_s[f] = 0.f;
    if (tid < 4 * IB * 2) ml_s[tid] = (tid & 1) ? 0.f : -1e30f;

    const size_t ebase = (size_t)(b * NN + i0) * NN * ED;

    for (int ch = 0; ch < NCH; ch++) {
        const int j0 = ch * NJ;
        __syncthreads();

        // ---- stage E (8 rows), NK, NV (fp16) ----
        #pragma unroll 4
        for (int f = tid; f < IB * 32 * 32; f += 128) {     // float2 units of E
            const int c2 = f & 31, j = (f >> 5) & 31, r = f >> 10;
            const float2 v = *(const float2*)(edge + ebase
                             + (size_t)r * NN * ED + (size_t)(j0 + j) * ED + c2 * 2);
            E2[r * 1152 + j * 36 + c2] = __floats2half2_rn(v.x, v.y);
        }
        #pragma unroll 4
        for (int f = tid; f < 32 * 64; f += 128) {          // float2 units of NK/NV
            const int t2 = f & 63, j = f >> 6;
            const size_t gi = (size_t)(b * NN + j0 + j) * ND + half * 128 + t2 * 2;
            const float2 k = *(const float2*)(d_nkp + gi);
            const float2 v = *(const float2*)(d_nvp + gi);
            NK2[j * 68 + t2] = __floats2half2_rn(k.x, k.y);
            NV2[j * 68 + t2] = __floats2half2_rn(v.x, v.y);
        }
        __syncthreads();

        #pragma unroll 1
        for (int r = 0; r < IB; r++) {
            const uint32_t* Er = (const uint32_t*)(E2 + r * 1152);

            // ---- A fragments (reused for Q and K gemms) ----
            uint32_t A[2][4][4];
            #pragma unroll
            for (int mt = 0; mt < 2; mt++)
                #pragma unroll
                for (int ks = 0; ks < 4; ks++) {
                    const int base = (16 * mt + g) * 36 + 8 * ks + tg;
                    A[mt][ks][0] = Er[base];
                    A[mt][ks][1] = Er[base + 8 * 36];
                    A[mt][ks][2] = Er[base + 4];
                    A[mt][ks][3] = Er[base + 8 * 36 + 4];
                }

            // ---- Q~ : init = scale*nq ----
            float cq[2][4][4];
            #pragma unroll
            for (int nt = 0; nt < 4; nt++) {
                const float2 q = *(const float2*)(nq_s + r * 128 + w * 32 + nt * 8 + 2 * tg);
                #pragma unroll
                for (int mt = 0; mt < 2; mt++) {
                    cq[mt][nt][0] = q.x; cq[mt][nt][1] = q.y;
                    cq[mt][nt][2] = q.x; cq[mt][nt][3] = q.y;
                }
            }
            #pragma unroll
            for (int ks = 0; ks < 4; ks++)
                #pragma unroll
                for (int mt = 0; mt < 2; mt++)
                    #pragma unroll
                    for (int nt = 0; nt < 4; nt++)
                        mma_f16(cq[mt][nt], A[mt][ks][0], A[mt][ks][1],
                                A[mt][ks][2], A[mt][ks][3],
                                bq[nt][ks][0], bq[nt][ks][1]);

            // ---- K~ : init = nk (fp16 staged) ----
            float ck[2][4][4];
            #pragma unroll
            for (int mt = 0; mt < 2; mt++) {
                const int jA = 16 * mt + g;
                #pragma unroll
                for (int nt = 0; nt < 4; nt++) {
                    const float2 k0 = __half22float2(NK2[jA * 68 + w * 16 + 4 * nt + tg]);
                    const float2 k1 = __half22float2(NK2[(jA + 8) * 68 + w * 16 + 4 * nt + tg]);
                    ck[mt][nt][0] = k0.x; ck[mt][nt][1] = k0.y;
                    ck[mt][nt][2] = k1.x; ck[mt][nt][3] = k1.y;
                }
            }
            #pragma unroll
            for (int ks = 0; ks < 4; ks++)
                #pragma unroll
                for (int mt = 0; mt < 2; mt++)
                    #pragma unroll
                    for (int nt = 0; nt < 4; nt++)
                        mma_f16(ck[mt][nt], A[mt][ks][0], A[mt][ks][1],
                                A[mt][ks][2], A[mt][ks][3],
                                bk[nt][ks][0], bk[nt][ks][1]);

            // ---- scores ----
            float s0[2], s1[2];
            #pragma unroll
            for (int mt = 0; mt < 2; mt++) {
                float a = 0.f, bb = 0.f;
                #pragma unroll
                for (int nt = 0; nt < 4; nt++) {
                    a  = fmaf(cq[mt][nt][0], ck[mt][nt][0], a);
                    a  = fmaf(cq[mt][nt][1], ck[mt][nt][1], a);
                    bb = fmaf(cq[mt][nt][2], ck[mt][nt][2], bb);
                    bb = fmaf(cq[mt][nt][3], ck[mt][nt][3], bb);
                }
                a  += __shfl_xor_sync(0xffffffffu, a, 1);
                a  += __shfl_xor_sync(0xffffffffu, a, 2);
                bb += __shfl_xor_sync(0xffffffffu, bb, 1);
                bb += __shfl_xor_sync(0xffffffffu, bb, 2);
                s0[mt] = a; s1[mt] = bb;
            }

            // ---- online softmax (warp-uniform per row) ----
            const float m_run = ml_s[(w * IB + r) * 2];
            const float l_run = ml_s[(w * IB + r) * 2 + 1];
            float mx = fmaxf(fmaxf(s0[0], s1[0]), fmaxf(s0[1], s1[1]));
            mx = fmaxf(mx, __shfl_xor_sync(0xffffffffu, mx, 4));
            mx = fmaxf(mx, __shfl_xor_sync(0xffffffffu, mx, 8));
            mx = fmaxf(mx, __shfl_xor_sync(0xffffffffu, mx, 16));
            const float mnew  = fmaxf(m_run, mx);
            const float alpha = __expf(m_run - mnew);

            float w0[2], w1[2];
            float ls = 0.f;
            #pragma unroll
            for (int mt = 0; mt < 2; mt++) {
                w0[mt] = __expf(s0[mt] - mnew);
                w1[mt] = __expf(s1[mt] - mnew);
                ls += w0[mt] + w1[mt];
            }
            ls += __shfl_xor_sync(0xffffffffu, ls, 4);
            ls += __shfl_xor_sync(0xffffffffu, ls, 8);
            ls += __shfl_xor_sync(0xffffffffu, ls, 16);

            if (lane == 0)
                *(float2*)(ml_s + (w * IB + r) * 2) =
                    make_float2(mnew, l_run * alpha + ls);
            if (tg == 0) {
                #pragma unroll
                for (int mt = 0; mt < 2; mt++) {
                    ws[w * 32 + 16 * mt + g]     = w0[mt];
                    ws[w * 32 + 16 * mt + g + 8] = w1[mt];
                }
            }
            __syncwarp();

            // ---- z / o_node update ----
            float z0 = z_s[(w * IB + r) * 64 + lane]      * alpha;
            float z1 = z_s[(w * IB + r) * 64 + lane + 32] * alpha;
            float on = on_s[(w * IB + r) * 32 + lane]     * alpha;
            #pragma unroll 4
            for (int j = 0; j < NJ; j++) {
                const float wv = ws[w * 32 + j];
                const float e0 = __half2float(E16[r * 2304 + j * 72 + lane]);
                const float e1 = __half2float(E16[r * 2304 + j * 72 + lane + 32]);
                const float nv = __half2float(NV16[j * 136 + w * 32 + lane]);
                z0 = fmaf(wv, e0, z0);
                z1 = fmaf(wv, e1, z1);
                on = fmaf(wv, nv, on);
            }
            z_s[(w * IB + r) * 64 + lane]      = z0;
            z_s[(w * IB + r) * 64 + lane + 32] = z1;
            on_s[(w * IB + r) * 32 + lane]     = on;
            __syncwarp();
        }
    }

    __syncthreads();

    // ---- epilogue: o = (o_node + z @ Wv^T) / l ----
    const size_t tglob = (size_t)(half * 128 + w * 32 + lane);
    #pragma unroll 1
    for (int r = 0; r < IB; r++) {
        float oe = 0.f;
        const float4* wvr = (const float4*)(Wev + tglob * ED);
        const float4* zr  = (const float4*)(z_s + (w * IB + r) * 64);
        #pragma unroll
        for (int c4 = 0; c4 < 16; c4++) {
            const float4 wv4 = __ldg(wvr + c4);
            const float4 z4  = zr[c4];
            oe = fmaf(z4.x, wv4.x, oe);
            oe = fmaf(z4.y, wv4.y, oe);
            oe = fmaf(z4.z, wv4.z, oe);
            oe = fmaf(z4.w, wv4.w, oe);
        }
        const float l = ml_s[(w * IB + r) * 2 + 1];
        out[(size_t)(b * NN + i0 + r) * ND + tglob] =
            (on_s[(w * IB + r) * 32 + lane] + oe) / l;
    }
}

// ---------------------------------------------------------------------------
extern "C" void kernel_launch(void* const* d_in, const int* in_sizes, int n_in,
                              void* d_out, int out_size)
{
    const float* node = (const float*)d_in[0];
    const float* edge = (const float*)d_in[1];
    const float* Wnq  = (const float*)d_in[2];
    const float* bnq  = (const float*)d_in[3];
    const float* Wnk  = (const float*)d_in[4];
    const float* bnk  = (const float*)d_in[5];
    const float* Wnv  = (const float*)d_in[6];
    const float* bnv  = (const float*)d_in[7];
    const float* Weq  = (const float*)d_in[8];
    const float* beq  = (const float*)d_in[9];
    const float* Wek  = (const float*)d_in[10];
    const float* bek  = (const float*)d_in[11];
    const float* Wev  = (const float*)d_in[12];
    const float* bev  = (const float*)d_in[13];
    float* out = (float*)d_out;

    cudaFuncSetAttribute(attn_mma_kernel,
                         cudaFuncAttributeMaxDynamicSharedMemorySize, SMEM_BYTES);

    node_proj_kernel<<<NB * NN / 8, 256>>>(node, Wnq, bnq, Wnk, bnk, Wnv, bnv,
                                           beq, bek, bev);
    attn_mma_kernel<<<NB * 64 * 2, 128, SMEM_BYTES>>>(edge, Weq, Wek, Wev, out);
}